// round 1
// baseline (speedup 1.0000x reference)
#include <cuda_runtime.h>
#include <math.h>

#define NN 100000
#define EE 1200000
#define FF 64
#define DD 32
#define GG 64

// ---------------- scratch (static __device__, no runtime allocation) ----------------
__device__ float g_Af[NN * FF];   // x_dst @ Wf[0:64]  + bf
__device__ float g_Bf[NN * FF];   // x_src @ Wf[64:128]
__device__ float g_As[NN * FF];   // x_dst @ Ws[0:64]  + bs
__device__ float g_Bs[NN * FF];   // x_src @ Ws[64:128]
__device__ float g_h [NN * FF];   // conv accumulator (init = x, residual folded in)
__device__ float g_x2[NN * FF];   // layer-1 output / layer-2 input
__device__ float g_gsum [GG * FF];
__device__ float g_gss  [GG * FF];
__device__ float g_alpha[GG * FF];
__device__ float g_beta [GG * FF];
__device__ float g_cnt[GG];
__device__ int   g_use64;         // 1 if index/batch buffers are int64, 0 if int32

// ---------------- int32/int64 runtime detection ----------------
// Indices are node ids in [0, 100000): stored as little-endian int64, every
// high 32-bit word is 0. Stored as int32, the "high word" of a pair is another
// random index (nonzero w.p. ~1-1e-5 per sample; 256 samples => certainty).
__global__ void k_detect(const int2* __restrict__ idx) {
    __shared__ int any;
    if (threadIdx.x == 0) any = 0;
    __syncthreads();
    int2 v = idx[threadIdx.x];
    if (v.y != 0) any = 1;
    __syncthreads();
    if (threadIdx.x == 0) g_use64 = (any == 0) ? 1 : 0;
}

// ---------------- node linear: Af,Bf,As,Bs + h = x ----------------
__global__ __launch_bounds__(256, 1) void k_node(
    const float* __restrict__ x,
    const float* __restrict__ Wf, const float* __restrict__ bf,
    const float* __restrict__ Ws, const float* __restrict__ bs)
{
    __shared__ float sW[64 * 64];   // one 64x64 W half at a time (16 KB)
    const int tid = threadIdx.x;
    const int n = blockIdx.x * 256 + tid;
    const bool act = (n < NN);

    float xr[64];
    if (act) {
        const float4* xp = (const float4*)(x + (size_t)n * FF);
        float4* hp = (float4*)(g_h + (size_t)n * FF);
        #pragma unroll
        for (int i = 0; i < 16; i++) {
            float4 v = xp[i];
            xr[4*i+0] = v.x; xr[4*i+1] = v.y; xr[4*i+2] = v.z; xr[4*i+3] = v.w;
            hp[i] = v;   // residual init
        }
    }

    for (int m = 0; m < 4; m++) {
        const float* Wsrc = ((m < 2) ? Wf : Ws) + (m & 1) * 4096;  // rows 0..63 or 64..127
        __syncthreads();
        for (int i = tid; i < 4096; i += 256) sW[i] = Wsrc[i];
        __syncthreads();
        if (!act) continue;

        float* dst = (m == 0 ? g_Af : m == 1 ? g_Bf : m == 2 ? g_As : g_Bs) + (size_t)n * FF;
        const float* bias = (m == 0) ? bf : (m == 2) ? bs : nullptr;

        #pragma unroll 1
        for (int c0 = 0; c0 < 64; c0 += 8) {
            float acc[8];
            #pragma unroll
            for (int j = 0; j < 8; j++) acc[j] = bias ? bias[c0 + j] : 0.f;
            #pragma unroll
            for (int k = 0; k < 64; k++) {          // broadcast LDS.128 reads of W
                float4 w0 = *(const float4*)&sW[k * 64 + c0];
                float4 w1 = *(const float4*)&sW[k * 64 + c0 + 4];
                float xv = xr[k];
                acc[0] += xv * w0.x; acc[1] += xv * w0.y;
                acc[2] += xv * w0.z; acc[3] += xv * w0.w;
                acc[4] += xv * w1.x; acc[5] += xv * w1.y;
                acc[6] += xv * w1.z; acc[7] += xv * w1.w;
            }
            #pragma unroll
            for (int j = 0; j < 8; j++) dst[c0 + j] = acc[j];
        }
    }
}

// ---------------- edge kernel: attr GEMV + gather + act + scatter ----------------
__device__ __forceinline__ float msgval(float f, float s) {
    // sigmoid(f) * softplus(s), numerically stable, fast-math
    float sig = __fdividef(1.f, 1.f + __expf(-f));
    float sp  = fmaxf(s, 0.f) + __logf(1.f + __expf(-fabsf(s)));
    return sig * sp;
}

__global__ __launch_bounds__(256, 1) void k_edge(
    const int* __restrict__ i32, const long long* __restrict__ i64,
    const float* __restrict__ attr,
    const float* __restrict__ Wf, const float* __restrict__ Ws)
{
    __shared__ float sF[32 * 64], sS[32 * 64];   // attr-part weights (16 KB)
    const int tid = threadIdx.x;
    for (int i = tid; i < 2048; i += 256) { sF[i] = Wf[8192 + i]; sS[i] = Ws[8192 + i]; }
    __syncthreads();

    const int e = blockIdx.x * 256 + tid;
    if (e >= EE) return;

    long long s, d;
    if (g_use64) { s = i64[e]; d = i64[EE + e]; }
    else         { s = i32[e]; d = i32[EE + e]; }

    float a[32];
    const float4* ap = (const float4*)(attr + (size_t)e * DD);
    #pragma unroll
    for (int i = 0; i < 8; i++) {
        float4 v = ap[i];
        a[4*i+0] = v.x; a[4*i+1] = v.y; a[4*i+2] = v.z; a[4*i+3] = v.w;
    }

    const float4* pAf = (const float4*)(g_Af + (size_t)d * FF);
    const float4* pBf = (const float4*)(g_Bf + (size_t)s * FF);
    const float4* pAs = (const float4*)(g_As + (size_t)d * FF);
    const float4* pBs = (const float4*)(g_Bs + (size_t)s * FF);
    float4* ph = (float4*)(g_h + (size_t)d * FF);

    #pragma unroll 1
    for (int c0 = 0; c0 < 64; c0 += 8) {
        const int q = c0 >> 2;
        float4 f0 = pAf[q], f1 = pAf[q+1], g0 = pBf[q], g1 = pBf[q+1];
        float4 s0 = pAs[q], s1 = pAs[q+1], t0 = pBs[q], t1 = pBs[q+1];
        float accf[8] = { f0.x+g0.x, f0.y+g0.y, f0.z+g0.z, f0.w+g0.w,
                          f1.x+g1.x, f1.y+g1.y, f1.z+g1.z, f1.w+g1.w };
        float accs[8] = { s0.x+t0.x, s0.y+t0.y, s0.z+t0.z, s0.w+t0.w,
                          s1.x+t1.x, s1.y+t1.y, s1.z+t1.z, s1.w+t1.w };
        #pragma unroll
        for (int k = 0; k < 32; k++) {
            float av = a[k];
            float4 wf0 = *(const float4*)&sF[k * 64 + c0];
            float4 wf1 = *(const float4*)&sF[k * 64 + c0 + 4];
            float4 ws0 = *(const float4*)&sS[k * 64 + c0];
            float4 ws1 = *(const float4*)&sS[k * 64 + c0 + 4];
            accf[0] += av * wf0.x; accf[1] += av * wf0.y;
            accf[2] += av * wf0.z; accf[3] += av * wf0.w;
            accf[4] += av * wf1.x; accf[5] += av * wf1.y;
            accf[6] += av * wf1.z; accf[7] += av * wf1.w;
            accs[0] += av * ws0.x; accs[1] += av * ws0.y;
            accs[2] += av * ws0.z; accs[3] += av * ws0.w;
            accs[4] += av * ws1.x; accs[5] += av * ws1.y;
            accs[6] += av * ws1.z; accs[7] += av * ws1.w;
        }
        float4 m0 = make_float4(msgval(accf[0], accs[0]), msgval(accf[1], accs[1]),
                                msgval(accf[2], accs[2]), msgval(accf[3], accs[3]));
        float4 m1 = make_float4(msgval(accf[4], accs[4]), msgval(accf[5], accs[5]),
                                msgval(accf[6], accs[6]), msgval(accf[7], accs[7]));
        atomicAdd(ph + q,     m0);   // vector red.global (sm_90+)
        atomicAdd(ph + q + 1, m1);
    }
}

// ---------------- graph-norm stats ----------------
__global__ void k_zero() {
    int i = blockIdx.x * 256 + threadIdx.x;
    if (i < GG * FF) { g_gsum[i] = 0.f; g_gss[i] = 0.f; }
}

__device__ __forceinline__ long long bget(const int* b32, const long long* b64, int u, int i) {
    return u ? b64[i] : (long long)b32[i];
}

__global__ __launch_bounds__(256, 1) void k_stats(const int* __restrict__ b32,
                                                  const long long* __restrict__ b64) {
    const int g = blockIdx.x >> 3;      // 8 splits per graph
    const int sp = blockIdx.x & 7;
    const int u = g_use64;

    int lo = 0, hi = NN;                // lower_bound(batch, g)  (batch sorted)
    while (lo < hi) { int mid = (lo + hi) >> 1; if (bget(b32, b64, u, mid) < (long long)g) lo = mid + 1; else hi = mid; }
    const int s0 = lo;
    hi = NN;                            // lower_bound(batch, g+1)
    while (lo < hi) { int mid = (lo + hi) >> 1; if (bget(b32, b64, u, mid) < (long long)(g + 1)) lo = mid + 1; else hi = mid; }
    const int s1 = lo;

    const int len = s1 - s0;
    const int chunk = (len + 7) >> 3;
    const int a = s0 + sp * chunk;
    const int b = min(a + chunk, s1);

    const int f = threadIdx.x & 63;
    const int j = threadIdx.x >> 6;
    float sum = 0.f, ss = 0.f;
    for (int n = a + j; n < b; n += 4) {
        float v = g_h[(size_t)n * FF + f];
        sum += v; ss += v * v;
    }
    __shared__ float r1[256], r2[256];
    r1[threadIdx.x] = sum; r2[threadIdx.x] = ss;
    __syncthreads();
    if (j == 0) {
        float t1 = r1[f] + r1[64 + f] + r1[128 + f] + r1[192 + f];
        float t2 = r2[f] + r2[64 + f] + r2[128 + f] + r2[192 + f];
        atomicAdd(&g_gsum[g * 64 + f], t1);
        atomicAdd(&g_gss [g * 64 + f], t2);
    }
    if (sp == 0 && threadIdx.x == 0) g_cnt[g] = (float)len;
}

__global__ void k_prep(const float* __restrict__ gw, const float* __restrict__ gb,
                       const float* __restrict__ gm) {
    int i = blockIdx.x * 256 + threadIdx.x;
    if (i >= GG * FF) return;
    int f = i & 63, g = i >> 6;
    float c    = fmaxf(g_cnt[g], 1.f);
    float inv  = __fdividef(1.f, c);
    float mean = g_gsum[i] * inv;
    float ex2  = g_gss[i] * inv;
    float sub  = gm[f] * mean;                       // ms * mean
    float var  = ex2 - 2.f * sub * mean + sub * sub; // E[(h-sub)^2]
    float rstd = rsqrtf(var + 1e-5f);
    float al   = gw[f] * rstd;
    g_alpha[i] = al;
    g_beta[i]  = gb[f] - al * sub;
}

__global__ void k_apply(float* __restrict__ out, const int* __restrict__ b32,
                        const long long* __restrict__ b64, int to_internal) {
    int i = blockIdx.x * 256 + threadIdx.x;
    if (i >= NN * FF) return;
    int n = i >> 6, f = i & 63;
    int g = g_use64 ? (int)b64[n] : b32[n];
    float y = g_alpha[g * 64 + f] * g_h[i] + g_beta[g * 64 + f];
    y = (y >= 0.f) ? y : 0.01f * y;      // LeakyReLU(0.01)
    if (to_internal) g_x2[i] = y; else out[i] = y;
}

// ---------------- launch ----------------
extern "C" void kernel_launch(void* const* d_in, const int* in_sizes, int n_in,
                              void* d_out, int out_size) {
    const float* x    = (const float*)d_in[0];
    const void*  idx  = d_in[1];
    const float* attr = (const float*)d_in[2];
    const void*  bat  = d_in[3];
    const float* Wf1 = (const float*)d_in[4];  const float* bf1 = (const float*)d_in[5];
    const float* Ws1 = (const float*)d_in[6];  const float* bs1 = (const float*)d_in[7];
    const float* gw1 = (const float*)d_in[8];  const float* gb1 = (const float*)d_in[9];
    const float* gm1 = (const float*)d_in[10];
    const float* Wf2 = (const float*)d_in[11]; const float* bf2 = (const float*)d_in[12];
    const float* Ws2 = (const float*)d_in[13]; const float* bs2 = (const float*)d_in[14];
    const float* gw2 = (const float*)d_in[15]; const float* gb2 = (const float*)d_in[16];
    const float* gm2 = (const float*)d_in[17];
    float* out = (float*)d_out;

    const int*       i32 = (const int*)idx;
    const long long* i64 = (const long long*)idx;
    const int*       b32 = (const int*)bat;
    const long long* b64 = (const long long*)bat;

    float* x2ptr = nullptr;
    cudaGetSymbolAddress((void**)&x2ptr, g_x2);

    const int NB_NODE = (NN + 255) / 256;        // 391
    const int NB_EDGE = (EE + 255) / 256;        // 4688
    const int NB_ELEM = (NN * FF) / 256;         // 25000

    k_detect<<<1, 256>>>((const int2*)idx);

    // layer 1
    k_node <<<NB_NODE, 256>>>(x, Wf1, bf1, Ws1, bs1);
    k_edge <<<NB_EDGE, 256>>>(i32, i64, attr, Wf1, Ws1);
    k_zero <<<16, 256>>>();
    k_stats<<<GG * 8, 256>>>(b32, b64);
    k_prep <<<16, 256>>>(gw1, gb1, gm1);
    k_apply<<<NB_ELEM, 256>>>(out, b32, b64, /*to_internal=*/1);

    // layer 2
    k_node <<<NB_NODE, 256>>>(x2ptr, Wf2, bf2, Ws2, bs2);
    k_edge <<<NB_EDGE, 256>>>(i32, i64, attr, Wf2, Ws2);
    k_zero <<<16, 256>>>();
    k_stats<<<GG * 8, 256>>>(b32, b64);
    k_prep <<<16, 256>>>(gw2, gb2, gm2);
    k_apply<<<NB_ELEM, 256>>>(out, b32, b64, /*to_internal=*/0);
}

// round 2
// speedup vs baseline: 1.0867x; 1.0867x over previous
#include <cuda_runtime.h>
#include <math.h>

#define NN 100000
#define EE 1200000
#define FF 64
#define DD 32
#define GG 64

// ---------------- scratch (static __device__, no runtime allocation) ----------------
__device__ float g_Af[NN * FF];   // x @ Wf[0:64]   + bf   (dst term)
__device__ float g_Bf[NN * FF];   // x @ Wf[64:128]        (src term)
__device__ float g_As[NN * FF];
__device__ float g_Bs[NN * FF];
__device__ float g_h [NN * FF];   // conv accumulator (init = x, residual folded in)
__device__ float g_x2[NN * FF];   // layer-1 output / layer-2 input
__device__ float g_gsum [GG * FF];
__device__ float g_gss  [GG * FF];
__device__ float g_alpha[GG * FF];
__device__ float g_beta [GG * FF];
__device__ float g_cnt[GG];
__device__ int   g_use64;         // 1 if index/batch buffers are int64, 0 if int32

// ---------------- int32/int64 runtime detection ----------------
__global__ void k_detect(const int2* __restrict__ idx) {
    __shared__ int any;
    if (threadIdx.x == 0) any = 0;
    __syncthreads();
    int2 v = idx[threadIdx.x];
    if (v.y != 0) any = 1;
    __syncthreads();
    if (threadIdx.x == 0) g_use64 = (any == 0) ? 1 : 0;
}

// ---------------- node linear: Af,Bf,As,Bs + h = x ----------------
// 8 lanes per node; lane l owns feature chunks l and l+8 (float4 each).
// Block = 256 threads = 8 warps = 32 nodes/block.
__global__ __launch_bounds__(256) void k_node(
    const float* __restrict__ x,
    const float* __restrict__ Wf, const float* __restrict__ bf,
    const float* __restrict__ Ws, const float* __restrict__ bs)
{
    __shared__ float sW[128 * 64];            // one full W matrix half-pair (32 KB)
    const int tid  = threadIdx.x;
    const int lane = tid & 31;
    const int l    = lane & 7;                // feature-chunk id
    const int sub  = lane >> 3;               // node within quad
    const int warp = tid >> 5;
    const int n    = (blockIdx.x * 8 + warp) * 4 + sub;
    const bool act = (n < NN);

    float xa0[4] = {0,0,0,0}, xa1[4] = {0,0,0,0};
    if (act) {
        const float4* xp = (const float4*)(x + (size_t)n * FF);
        float4 v0 = xp[l], v1 = xp[l + 8];
        xa0[0]=v0.x; xa0[1]=v0.y; xa0[2]=v0.z; xa0[3]=v0.w;
        xa1[0]=v1.x; xa1[1]=v1.y; xa1[2]=v1.z; xa1[3]=v1.w;
        float4* hp = (float4*)(g_h + (size_t)n * FF);
        hp[l] = v0; hp[l + 8] = v1;           // residual init, coalesced
    }

    const float4* sW4 = (const float4*)sW;

    #pragma unroll 1
    for (int m = 0; m < 2; m++) {
        const float* Wsrc = (m == 0) ? Wf : Ws;
        const float* bias = (m == 0) ? bf : bs;
        __syncthreads();
        for (int i = tid; i < 8192; i += 256) sW[i] = Wsrc[i];
        __syncthreads();

        float accA[8], accB[8];
        #pragma unroll
        for (int j = 0; j < 4; j++) { accA[j] = bias[4*l + j]; accA[4+j] = bias[32 + 4*l + j]; }
        #pragma unroll
        for (int j = 0; j < 8; j++) accB[j] = 0.f;

        #pragma unroll
        for (int k = 0; k < 64; k++) {
            const int src = (lane & 24) | ((k >> 2) & 7);
            float xv = __shfl_sync(0xffffffffu, (k < 32) ? xa0[k & 3] : xa1[k & 3], src);
            float4 wa0 = sW4[k * 16 + l];
            float4 wa1 = sW4[k * 16 + 8 + l];
            float4 wb0 = sW4[(64 + k) * 16 + l];
            float4 wb1 = sW4[(64 + k) * 16 + 8 + l];
            accA[0] += xv * wa0.x; accA[1] += xv * wa0.y; accA[2] += xv * wa0.z; accA[3] += xv * wa0.w;
            accA[4] += xv * wa1.x; accA[5] += xv * wa1.y; accA[6] += xv * wa1.z; accA[7] += xv * wa1.w;
            accB[0] += xv * wb0.x; accB[1] += xv * wb0.y; accB[2] += xv * wb0.z; accB[3] += xv * wb0.w;
            accB[4] += xv * wb1.x; accB[5] += xv * wb1.y; accB[6] += xv * wb1.z; accB[7] += xv * wb1.w;
        }

        if (act) {
            float4* dA = (float4*)((m == 0 ? g_Af : g_As) + (size_t)n * FF);
            float4* dB = (float4*)((m == 0 ? g_Bf : g_Bs) + (size_t)n * FF);
            dA[l]     = make_float4(accA[0], accA[1], accA[2], accA[3]);
            dA[l + 8] = make_float4(accA[4], accA[5], accA[6], accA[7]);
            dB[l]     = make_float4(accB[0], accB[1], accB[2], accB[3]);
            dB[l + 8] = make_float4(accB[4], accB[5], accB[6], accB[7]);
        }
    }
}

// ---------------- edge kernel: attr GEMV + gather + act + scatter ----------------
__device__ __forceinline__ float msgval(float f, float s) {
    float sig = __fdividef(1.f, 1.f + __expf(-f));
    float sp  = fmaxf(s, 0.f) + __logf(1.f + __expf(-fabsf(s)));
    return sig * sp;
}

// 8 lanes per edge; lane l owns feature chunks l, l+8. Warp = 4 edges per pass,
// QPW passes per warp. Block = 8 warps.
#define QPW 4
__global__ __launch_bounds__(256) void k_edge(
    const int* __restrict__ i32, const long long* __restrict__ i64,
    const float* __restrict__ attr,
    const float* __restrict__ Wf, const float* __restrict__ Ws)
{
    __shared__ float sF[32 * 64], sS[32 * 64];   // attr-part weights (16 KB)
    const int tid = threadIdx.x;
    for (int i = tid; i < 2048; i += 256) { sF[i] = Wf[8192 + i]; sS[i] = Ws[8192 + i]; }
    __syncthreads();

    const int lane = tid & 31;
    const int l    = lane & 7;
    const int sub  = lane >> 3;
    const int warp = tid >> 5;
    const int use64 = g_use64;
    const float4* sF4 = (const float4*)sF;
    const float4* sS4 = (const float4*)sS;

    const int base = (blockIdx.x * 8 + warp) * (4 * QPW);

    #pragma unroll 1
    for (int q = 0; q < QPW; q++) {
        const int e = base + q * 4 + sub;     // EE divides grid coverage exactly

        long long s, d;
        if (use64) { s = i64[e]; d = i64[EE + e]; }
        else       { s = i32[e]; d = i32[EE + e]; }

        float4 av = ((const float4*)attr)[(size_t)e * 8 + l];
        float aval[4] = { av.x, av.y, av.z, av.w };

        const float4* pAf = (const float4*)(g_Af + (size_t)d * FF);
        const float4* pBf = (const float4*)(g_Bf + (size_t)s * FF);
        const float4* pAs = (const float4*)(g_As + (size_t)d * FF);
        const float4* pBs = (const float4*)(g_Bs + (size_t)s * FF);

        float4 f0 = pAf[l], f1 = pAf[l + 8];
        float4 g0 = pBf[l], g1 = pBf[l + 8];
        float4 s0 = pAs[l], s1 = pAs[l + 8];
        float4 t0 = pBs[l], t1 = pBs[l + 8];

        float accf[8] = { f0.x+g0.x, f0.y+g0.y, f0.z+g0.z, f0.w+g0.w,
                          f1.x+g1.x, f1.y+g1.y, f1.z+g1.z, f1.w+g1.w };
        float accs[8] = { s0.x+t0.x, s0.y+t0.y, s0.z+t0.z, s0.w+t0.w,
                          s1.x+t1.x, s1.y+t1.y, s1.z+t1.z, s1.w+t1.w };

        #pragma unroll
        for (int k = 0; k < 32; k++) {
            const int src = (lane & 24) | (k >> 2);
            float ak = __shfl_sync(0xffffffffu, aval[k & 3], src);
            float4 wf0 = sF4[k * 16 + l];
            float4 wf1 = sF4[k * 16 + 8 + l];
            float4 ws0 = sS4[k * 16 + l];
            float4 ws1 = sS4[k * 16 + 8 + l];
            accf[0] += ak * wf0.x; accf[1] += ak * wf0.y; accf[2] += ak * wf0.z; accf[3] += ak * wf0.w;
            accf[4] += ak * wf1.x; accf[5] += ak * wf1.y; accf[6] += ak * wf1.z; accf[7] += ak * wf1.w;
            accs[0] += ak * ws0.x; accs[1] += ak * ws0.y; accs[2] += ak * ws0.z; accs[3] += ak * ws0.w;
            accs[4] += ak * ws1.x; accs[5] += ak * ws1.y; accs[6] += ak * ws1.z; accs[7] += ak * ws1.w;
        }

        float4 m0 = make_float4(msgval(accf[0], accs[0]), msgval(accf[1], accs[1]),
                                msgval(accf[2], accs[2]), msgval(accf[3], accs[3]));
        float4 m1 = make_float4(msgval(accf[4], accs[4]), msgval(accf[5], accs[5]),
                                msgval(accf[6], accs[6]), msgval(accf[7], accs[7]));
        float4* ph = (float4*)(g_h + (size_t)d * FF);
        atomicAdd(ph + l,     m0);   // coalesced vector red (sm_90+)
        atomicAdd(ph + l + 8, m1);
    }
}

// ---------------- graph-norm ----------------
__global__ void k_zero() {
    int i = blockIdx.x * 256 + threadIdx.x;
    if (i < GG * FF) { g_gsum[i] = 0.f; g_gss[i] = 0.f; }
}

__device__ __forceinline__ long long bget(const int* b32, const long long* b64, int u, int i) {
    return u ? b64[i] : (long long)b32[i];
}

__global__ __launch_bounds__(256) void k_stats(const int* __restrict__ b32,
                                               const long long* __restrict__ b64) {
    const int g = blockIdx.x >> 3;      // 8 splits per graph
    const int sp = blockIdx.x & 7;
    const int u = g_use64;

    int lo = 0, hi = NN;
    while (lo < hi) { int mid = (lo + hi) >> 1; if (bget(b32, b64, u, mid) < (long long)g) lo = mid + 1; else hi = mid; }
    const int s0 = lo;
    hi = NN;
    while (lo < hi) { int mid = (lo + hi) >> 1; if (bget(b32, b64, u, mid) < (long long)(g + 1)) lo = mid + 1; else hi = mid; }
    const int s1 = lo;

    const int len = s1 - s0;
    const int chunk = (len + 7) >> 3;
    const int a = s0 + sp * chunk;
    const int b = min(a + chunk, s1);

    const int f = threadIdx.x & 63;
    const int j = threadIdx.x >> 6;
    float sum = 0.f, ss = 0.f;
    for (int n = a + j; n < b; n += 4) {
        float v = g_h[(size_t)n * FF + f];
        sum += v; ss += v * v;
    }
    __shared__ float r1[256], r2[256];
    r1[threadIdx.x] = sum; r2[threadIdx.x] = ss;
    __syncthreads();
    if (j == 0) {
        float t1 = r1[f] + r1[64 + f] + r1[128 + f] + r1[192 + f];
        float t2 = r2[f] + r2[64 + f] + r2[128 + f] + r2[192 + f];
        atomicAdd(&g_gsum[g * 64 + f], t1);
        atomicAdd(&g_gss [g * 64 + f], t2);
    }
    if (sp == 0 && threadIdx.x == 0) g_cnt[g] = (float)len;
}

__global__ void k_prep(const float* __restrict__ gw, const float* __restrict__ gb,
                       const float* __restrict__ gm) {
    int i = blockIdx.x * 256 + threadIdx.x;
    if (i >= GG * FF) return;
    int f = i & 63, g = i >> 6;
    float c    = fmaxf(g_cnt[g], 1.f);
    float inv  = __fdividef(1.f, c);
    float mean = g_gsum[i] * inv;
    float ex2  = g_gss[i] * inv;
    float sub  = gm[f] * mean;
    float var  = ex2 - 2.f * sub * mean + sub * sub;
    float rstd = rsqrtf(var + 1e-5f);
    float al   = gw[f] * rstd;
    g_alpha[i] = al;
    g_beta[i]  = gb[f] - al * sub;
}

__global__ void k_apply(float* __restrict__ out, const int* __restrict__ b32,
                        const long long* __restrict__ b64, int to_internal) {
    int i = blockIdx.x * 256 + threadIdx.x;
    if (i >= NN * FF) return;
    int n = i >> 6, f = i & 63;
    int g = g_use64 ? (int)b64[n] : b32[n];
    float y = g_alpha[g * 64 + f] * g_h[i] + g_beta[g * 64 + f];
    y = (y >= 0.f) ? y : 0.01f * y;
    if (to_internal) g_x2[i] = y; else out[i] = y;
}

// ---------------- launch ----------------
extern "C" void kernel_launch(void* const* d_in, const int* in_sizes, int n_in,
                              void* d_out, int out_size) {
    const float* x    = (const float*)d_in[0];
    const void*  idx  = d_in[1];
    const float* attr = (const float*)d_in[2];
    const void*  bat  = d_in[3];
    const float* Wf1 = (const float*)d_in[4];  const float* bf1 = (const float*)d_in[5];
    const float* Ws1 = (const float*)d_in[6];  const float* bs1 = (const float*)d_in[7];
    const float* gw1 = (const float*)d_in[8];  const float* gb1 = (const float*)d_in[9];
    const float* gm1 = (const float*)d_in[10];
    const float* Wf2 = (const float*)d_in[11]; const float* bf2 = (const float*)d_in[12];
    const float* Ws2 = (const float*)d_in[13]; const float* bs2 = (const float*)d_in[14];
    const float* gw2 = (const float*)d_in[15]; const float* gb2 = (const float*)d_in[16];
    const float* gm2 = (const float*)d_in[17];
    float* out = (float*)d_out;

    const int*       i32 = (const int*)idx;
    const long long* i64 = (const long long*)idx;
    const int*       b32 = (const int*)bat;
    const long long* b64 = (const long long*)bat;

    float* x2ptr = nullptr;
    cudaGetSymbolAddress((void**)&x2ptr, g_x2);

    const int NB_NODE = (NN + 31) / 32;              // 32 nodes / block
    const int NB_EDGE = EE / (32 * QPW);             // 128 edges / block -> 9375
    const int NB_ELEM = (NN * FF) / 256;

    k_detect<<<1, 256>>>((const int2*)idx);

    // layer 1
    k_node <<<NB_NODE, 256>>>(x, Wf1, bf1, Ws1, bs1);
    k_edge <<<NB_EDGE, 256>>>(i32, i64, attr, Wf1, Ws1);
    k_zero <<<16, 256>>>();
    k_stats<<<GG * 8, 256>>>(b32, b64);
    k_prep <<<16, 256>>>(gw1, gb1, gm1);
    k_apply<<<NB_ELEM, 256>>>(out, b32, b64, 1);

    // layer 2
    k_node <<<NB_NODE, 256>>>(x2ptr, Wf2, bf2, Ws2, bs2);
    k_edge <<<NB_EDGE, 256>>>(i32, i64, attr, Wf2, Ws2);
    k_zero <<<16, 256>>>();
    k_stats<<<GG * 8, 256>>>(b32, b64);
    k_prep <<<16, 256>>>(gw2, gb2, gm2);
    k_apply<<<NB_ELEM, 256>>>(out, b32, b64, 0);
}

// round 3
// speedup vs baseline: 1.5311x; 1.4089x over previous
#include <cuda_runtime.h>
#include <math.h>

#define NN 100000
#define EE 1200000
#define FF 64
#define DD 32
#define GG 64

// ---------------- scratch (static __device__, no runtime allocation) ----------------
__device__ float g_Af[NN * FF];   // x @ Wf[0:64]   + bf   (dst term)
__device__ float g_Bf[NN * FF];   // x @ Wf[64:128]        (src term)
__device__ float g_As[NN * FF];
__device__ float g_Bs[NN * FF];
__device__ float g_h [NN * FF];   // conv accumulator (init = x, residual folded in)
__device__ float g_x2[NN * FF];   // layer-1 output / layer-2 input
__device__ float g_gsum [GG * FF];
__device__ float g_gss  [GG * FF];
__device__ float g_alpha[GG * FF];
__device__ float g_beta [GG * FF];
__device__ float g_cnt[GG];
__device__ int   g_use64;

// ---------------- int32/int64 runtime detection ----------------
__global__ void k_detect(const int2* __restrict__ idx) {
    __shared__ int any;
    if (threadIdx.x == 0) any = 0;
    __syncthreads();
    int2 v = idx[threadIdx.x];
    if (v.y != 0) any = 1;
    __syncthreads();
    if (threadIdx.x == 0) g_use64 = (any == 0) ? 1 : 0;
}

// ---------------- node linear: Af,Bf,As,Bs + h = x ----------------
// 8 lanes per node, 2 nodes per thread (weight reuse), 8 nodes/warp/pass.
__global__ __launch_bounds__(256, 1) void k_node(
    const float* __restrict__ x,
    const float* __restrict__ Wf, const float* __restrict__ bf,
    const float* __restrict__ Ws, const float* __restrict__ bs)
{
    __shared__ float sW[128 * 64];            // full W (32 KB)
    const int tid  = threadIdx.x;
    const int lane = tid & 31;
    const int l    = lane & 7;
    const int sub  = lane >> 3;
    const int warp = tid >> 5;
    const int nb   = (blockIdx.x * 8 + warp) * 8 + sub;   // nodes nb, nb+4

    float xa[2][8];
    bool act[2];
    #pragma unroll
    for (int j = 0; j < 2; j++) {
        const int n = nb + 4 * j;
        act[j] = (n < NN);
        if (act[j]) {
            const float4* xp = (const float4*)(x + (size_t)n * FF);
            float4 v0 = xp[l], v1 = xp[l + 8];
            xa[j][0]=v0.x; xa[j][1]=v0.y; xa[j][2]=v0.z; xa[j][3]=v0.w;
            xa[j][4]=v1.x; xa[j][5]=v1.y; xa[j][6]=v1.z; xa[j][7]=v1.w;
            float4* hp = (float4*)(g_h + (size_t)n * FF);
            hp[l] = v0; hp[l + 8] = v1;
        } else {
            #pragma unroll
            for (int t = 0; t < 8; t++) xa[j][t] = 0.f;
        }
    }

    const float4* sW4 = (const float4*)sW;

    #pragma unroll 1
    for (int m = 0; m < 2; m++) {
        const float* Wsrc = (m == 0) ? Wf : Ws;
        const float* bias = (m == 0) ? bf : bs;
        __syncthreads();
        for (int i = tid; i < 8192; i += 256) sW[i] = Wsrc[i];
        __syncthreads();

        float accA[2][8], accB[2][8];
        #pragma unroll
        for (int j = 0; j < 2; j++) {
            #pragma unroll
            for (int t = 0; t < 4; t++) {
                accA[j][t]   = bias[4*l + t];
                accA[j][4+t] = bias[32 + 4*l + t];
                accB[j][t]   = 0.f;
                accB[j][4+t] = 0.f;
            }
        }

        #pragma unroll
        for (int k = 0; k < 64; k++) {
            const int src = (lane & 24) | ((k >> 2) & 7);
            float4 wa0 = sW4[k * 16 + l];
            float4 wa1 = sW4[k * 16 + 8 + l];
            float4 wb0 = sW4[(64 + k) * 16 + l];
            float4 wb1 = sW4[(64 + k) * 16 + 8 + l];
            #pragma unroll
            for (int j = 0; j < 2; j++) {
                float xv = __shfl_sync(0xffffffffu, (k < 32) ? xa[j][k & 3] : xa[j][4 + (k & 3)], src);
                accA[j][0] += xv * wa0.x; accA[j][1] += xv * wa0.y; accA[j][2] += xv * wa0.z; accA[j][3] += xv * wa0.w;
                accA[j][4] += xv * wa1.x; accA[j][5] += xv * wa1.y; accA[j][6] += xv * wa1.z; accA[j][7] += xv * wa1.w;
                accB[j][0] += xv * wb0.x; accB[j][1] += xv * wb0.y; accB[j][2] += xv * wb0.z; accB[j][3] += xv * wb0.w;
                accB[j][4] += xv * wb1.x; accB[j][5] += xv * wb1.y; accB[j][6] += xv * wb1.z; accB[j][7] += xv * wb1.w;
            }
        }

        #pragma unroll
        for (int j = 0; j < 2; j++) {
            if (!act[j]) continue;
            const int n = nb + 4 * j;
            float4* dA = (float4*)((m == 0 ? g_Af : g_As) + (size_t)n * FF);
            float4* dB = (float4*)((m == 0 ? g_Bf : g_Bs) + (size_t)n * FF);
            dA[l]     = make_float4(accA[j][0], accA[j][1], accA[j][2], accA[j][3]);
            dA[l + 8] = make_float4(accA[j][4], accA[j][5], accA[j][6], accA[j][7]);
            dB[l]     = make_float4(accB[j][0], accB[j][1], accB[j][2], accB[j][3]);
            dB[l + 8] = make_float4(accB[j][4], accB[j][5], accB[j][6], accB[j][7]);
        }
    }
}

// ---------------- edge kernel ----------------
__device__ __forceinline__ float msgval(float f, float s) {
    float sig = __fdividef(1.f, 1.f + __expf(-f));
    float sp  = fmaxf(s, 0.f) + __logf(1.f + __expf(-fabsf(s)));
    return sig * sp;
}

// 8 lanes per edge, 4 edges per thread in the k-loop (weight reuse x4).
// Warp = 16 edges, block = 8 warps = 128 edges. EE % 128 == 0.
__global__ __launch_bounds__(256, 1) void k_edge(
    const int* __restrict__ i32, const long long* __restrict__ i64,
    const float* __restrict__ attr,
    const float* __restrict__ Wf, const float* __restrict__ Ws)
{
    __shared__ float sF[2048], sS[2048];
    const int tid = threadIdx.x;
    for (int i = tid; i < 2048; i += 256) { sF[i] = Wf[8192 + i]; sS[i] = Ws[8192 + i]; }
    __syncthreads();

    const int lane = tid & 31;
    const int l    = lane & 7;
    const int sub  = lane >> 3;
    const int warp = tid >> 5;
    const int use64 = g_use64;
    const float4* sF4 = (const float4*)sF;
    const float4* sS4 = (const float4*)sS;

    const int ebase = blockIdx.x * 128 + warp * 16 + sub;  // edges ebase + 4j

    int dIdx[4];
    float av[4][4];
    float accf[4][8], accs[4][8];

    #pragma unroll
    for (int j = 0; j < 4; j++) {
        const int e = ebase + 4 * j;
        long long s, d;
        if (use64) { s = i64[e]; d = i64[EE + e]; }
        else       { s = i32[e]; d = i32[EE + e]; }
        dIdx[j] = (int)d;

        float4 a = ((const float4*)attr)[(size_t)e * 8 + l];
        av[j][0] = a.x; av[j][1] = a.y; av[j][2] = a.z; av[j][3] = a.w;

        const float4* pAf = (const float4*)(g_Af + (size_t)d * FF);
        const float4* pBf = (const float4*)(g_Bf + (size_t)s * FF);
        const float4* pAs = (const float4*)(g_As + (size_t)d * FF);
        const float4* pBs = (const float4*)(g_Bs + (size_t)s * FF);
        float4 f0 = pAf[l], f1 = pAf[l + 8];
        float4 g0 = pBf[l], g1 = pBf[l + 8];
        float4 s0 = pAs[l], s1 = pAs[l + 8];
        float4 t0 = pBs[l], t1 = pBs[l + 8];
        accf[j][0]=f0.x+g0.x; accf[j][1]=f0.y+g0.y; accf[j][2]=f0.z+g0.z; accf[j][3]=f0.w+g0.w;
        accf[j][4]=f1.x+g1.x; accf[j][5]=f1.y+g1.y; accf[j][6]=f1.z+g1.z; accf[j][7]=f1.w+g1.w;
        accs[j][0]=s0.x+t0.x; accs[j][1]=s0.y+t0.y; accs[j][2]=s0.z+t0.z; accs[j][3]=s0.w+t0.w;
        accs[j][4]=s1.x+t1.x; accs[j][5]=s1.y+t1.y; accs[j][6]=s1.z+t1.z; accs[j][7]=s1.w+t1.w;
    }

    #pragma unroll
    for (int k = 0; k < 32; k++) {
        const int src = (lane & 24) | (k >> 2);
        float4 wf0 = sF4[k * 16 + l];
        float4 wf1 = sF4[k * 16 + 8 + l];
        float4 ws0 = sS4[k * 16 + l];
        float4 ws1 = sS4[k * 16 + 8 + l];
        #pragma unroll
        for (int j = 0; j < 4; j++) {
            float ak = __shfl_sync(0xffffffffu, av[j][k & 3], src);
            accf[j][0] += ak * wf0.x; accf[j][1] += ak * wf0.y; accf[j][2] += ak * wf0.z; accf[j][3] += ak * wf0.w;
            accf[j][4] += ak * wf1.x; accf[j][5] += ak * wf1.y; accf[j][6] += ak * wf1.z; accf[j][7] += ak * wf1.w;
            accs[j][0] += ak * ws0.x; accs[j][1] += ak * ws0.y; accs[j][2] += ak * ws0.z; accs[j][3] += ak * ws0.w;
            accs[j][4] += ak * ws1.x; accs[j][5] += ak * ws1.y; accs[j][6] += ak * ws1.z; accs[j][7] += ak * ws1.w;
        }
    }

    #pragma unroll
    for (int j = 0; j < 4; j++) {
        float4 m0 = make_float4(msgval(accf[j][0], accs[j][0]), msgval(accf[j][1], accs[j][1]),
                                msgval(accf[j][2], accs[j][2]), msgval(accf[j][3], accs[j][3]));
        float4 m1 = make_float4(msgval(accf[j][4], accs[j][4]), msgval(accf[j][5], accs[j][5]),
                                msgval(accf[j][6], accs[j][6]), msgval(accf[j][7], accs[j][7]));
        float4* ph = (float4*)(g_h + (size_t)dIdx[j] * FF);
        atomicAdd(ph + l,     m0);
        atomicAdd(ph + l + 8, m1);
    }
}

// ---------------- graph-norm ----------------
__global__ void k_zero() {
    int i = blockIdx.x * 256 + threadIdx.x;
    if (i < GG * FF) { g_gsum[i] = 0.f; g_gss[i] = 0.f; }
}

__device__ __forceinline__ long long bget(const int* b32, const long long* b64, int u, int i) {
    return u ? b64[i] : (long long)b32[i];
}

__global__ __launch_bounds__(256) void k_stats(const int* __restrict__ b32,
                                               const long long* __restrict__ b64) {
    const int g = blockIdx.x >> 3;
    const int sp = blockIdx.x & 7;
    const int u = g_use64;

    int lo = 0, hi = NN;
    while (lo < hi) { int mid = (lo + hi) >> 1; if (bget(b32, b64, u, mid) < (long long)g) lo = mid + 1; else hi = mid; }
    const int s0 = lo;
    hi = NN;
    while (lo < hi) { int mid = (lo + hi) >> 1; if (bget(b32, b64, u, mid) < (long long)(g + 1)) lo = mid + 1; else hi = mid; }
    const int s1 = lo;

    const int len = s1 - s0;
    const int chunk = (len + 7) >> 3;
    const int a = s0 + sp * chunk;
    const int b = min(a + chunk, s1);

    const int f = threadIdx.x & 63;
    const int j = threadIdx.x >> 6;
    float sum = 0.f, ss = 0.f;
    for (int n = a + j; n < b; n += 4) {
        float v = g_h[(size_t)n * FF + f];
        sum += v; ss += v * v;
    }
    __shared__ float r1[256], r2[256];
    r1[threadIdx.x] = sum; r2[threadIdx.x] = ss;
    __syncthreads();
    if (j == 0) {
        float t1 = r1[f] + r1[64 + f] + r1[128 + f] + r1[192 + f];
        float t2 = r2[f] + r2[64 + f] + r2[128 + f] + r2[192 + f];
        atomicAdd(&g_gsum[g * 64 + f], t1);
        atomicAdd(&g_gss [g * 64 + f], t2);
    }
    if (sp == 0 && threadIdx.x == 0) g_cnt[g] = (float)len;
}

__global__ void k_prep(const float* __restrict__ gw, const float* __restrict__ gb,
                       const float* __restrict__ gm) {
    int i = blockIdx.x * 256 + threadIdx.x;
    if (i >= GG * FF) return;
    int f = i & 63, g = i >> 6;
    float c    = fmaxf(g_cnt[g], 1.f);
    float inv  = __fdividef(1.f, c);
    float mean = g_gsum[i] * inv;
    float ex2  = g_gss[i] * inv;
    float sub  = gm[f] * mean;
    float var  = ex2 - 2.f * sub * mean + sub * sub;
    float rstd = rsqrtf(var + 1e-5f);
    float al   = gw[f] * rstd;
    g_alpha[i] = al;
    g_beta[i]  = gb[f] - al * sub;
}

__global__ void k_apply(float* __restrict__ out, const int* __restrict__ b32,
                        const long long* __restrict__ b64, int to_internal) {
    int i = blockIdx.x * 256 + threadIdx.x;
    if (i >= NN * FF) return;
    int n = i >> 6, f = i & 63;
    int g = g_use64 ? (int)b64[n] : b32[n];
    float y = g_alpha[g * 64 + f] * g_h[i] + g_beta[g * 64 + f];
    y = (y >= 0.f) ? y : 0.01f * y;
    if (to_internal) g_x2[i] = y; else out[i] = y;
}

// ---------------- launch ----------------
extern "C" void kernel_launch(void* const* d_in, const int* in_sizes, int n_in,
                              void* d_out, int out_size) {
    const float* x    = (const float*)d_in[0];
    const void*  idx  = d_in[1];
    const float* attr = (const float*)d_in[2];
    const void*  bat  = d_in[3];
    const float* Wf1 = (const float*)d_in[4];  const float* bf1 = (const float*)d_in[5];
    const float* Ws1 = (const float*)d_in[6];  const float* bs1 = (const float*)d_in[7];
    const float* gw1 = (const float*)d_in[8];  const float* gb1 = (const float*)d_in[9];
    const float* gm1 = (const float*)d_in[10];
    const float* Wf2 = (const float*)d_in[11]; const float* bf2 = (const float*)d_in[12];
    const float* Ws2 = (const float*)d_in[13]; const float* bs2 = (const float*)d_in[14];
    const float* gw2 = (const float*)d_in[15]; const float* gb2 = (const float*)d_in[16];
    const float* gm2 = (const float*)d_in[17];
    float* out = (float*)d_out;

    const int*       i32 = (const int*)idx;
    const long long* i64 = (const long long*)idx;
    const int*       b32 = (const int*)bat;
    const long long* b64 = (const long long*)bat;

    float* x2ptr = nullptr;
    cudaGetSymbolAddress((void**)&x2ptr, g_x2);

    const int NB_NODE = (NN + 63) / 64;      // 64 nodes / block
    const int NB_EDGE = EE / 128;            // 9375
    const int NB_ELEM = (NN * FF) / 256;

    k_detect<<<1, 256>>>((const int2*)idx);

    // layer 1  (zero moved before edge so ncu -s 5 lands on k_edge)
    k_node <<<NB_NODE, 256>>>(x, Wf1, bf1, Ws1, bs1);
    k_zero <<<16, 256>>>();
    k_edge <<<NB_EDGE, 256>>>(i32, i64, attr, Wf1, Ws1);
    k_stats<<<GG * 8, 256>>>(b32, b64);
    k_prep <<<16, 256>>>(gw1, gb1, gm1);
    k_apply<<<NB_ELEM, 256>>>(out, b32, b64, 1);

    // layer 2
    k_node <<<NB_NODE, 256>>>(x2ptr, Wf2, bf2, Ws2, bs2);
    k_zero <<<16, 256>>>();
    k_edge <<<NB_EDGE, 256>>>(i32, i64, attr, Wf2, Ws2);
    k_stats<<<GG * 8, 256>>>(b32, b64);
    k_prep <<<16, 256>>>(gw2, gb2, gm2);
    k_apply<<<NB_ELEM, 256>>>(out, b32, b64, 0);
}